// round 12
// baseline (speedup 1.0000x reference)
#include <cuda_runtime.h>
#include <cuda_fp16.h>
#include <cstdint>

#define T_DIM 4096
#define H_DIM 2048
#define F_DIM 7168

// ---------------- scratch (device globals; no runtime allocation) ------------
__device__ __align__(1024) __half g_xh  [(size_t)T_DIM * H_DIM];   // x  fp16 [T,H]
__device__ __align__(1024) __half g_w1h [(size_t)F_DIM * H_DIM];   // w1 fp16 [F,H]
__device__ __align__(1024) __half g_w3h [(size_t)F_DIM * H_DIM];   // w3 fp16 [F,H]
__device__ __align__(1024) __half g_w2h [(size_t)H_DIM * F_DIM];   // w2 fp16 [H,F]
__device__ __align__(1024) __half g_fused[(size_t)T_DIM * F_DIM];  // silu(g)*u fp16 [T,F]

// ---------------- helpers -----------------------------------------------------
__device__ __forceinline__ float silu_f(float v) { return v / (1.0f + __expf(-v)); }

__device__ __forceinline__ uint32_t smem_u32(const void* p) {
    uint32_t a;
    asm("{ .reg .u64 t; cvta.to.shared.u64 t, %1; cvt.u32.u64 %0, t; }" : "=r"(a) : "l"(p));
    return a;
}

#define SW128(o) ((o) ^ (((o) >> 3) & 0x70))

__device__ __forceinline__ void cp16(uint32_t dst, const void* src) {
    asm volatile("cp.async.cg.shared.global [%0], [%1], 16;\n" :: "r"(dst), "l"(src));
}

__device__ __forceinline__ void mma16816(float c[4], const uint32_t a[4], const uint32_t b[2]) {
    asm volatile(
        "mma.sync.aligned.m16n8k16.row.col.f32.f16.f16.f32 "
        "{%0,%1,%2,%3}, {%4,%5,%6,%7}, {%8,%9}, {%0,%1,%2,%3};\n"
        : "+f"(c[0]), "+f"(c[1]), "+f"(c[2]), "+f"(c[3])
        : "r"(a[0]), "r"(a[1]), "r"(a[2]), "r"(a[3]), "r"(b[0]), "r"(b[1]));
}

__device__ __forceinline__ void ldsm4(uint32_t* r, uint32_t addr) {
    asm volatile("ldmatrix.sync.aligned.m8n8.x4.shared.b16 {%0,%1,%2,%3}, [%4];"
                 : "=r"(r[0]), "=r"(r[1]), "=r"(r[2]), "=r"(r[3]) : "r"(addr));
}

// ---------------- dequant body (compile-time shapes) ---------------------------
template <int N, int K>
__device__ __forceinline__ void dequant_span(const float4* __restrict__ wq,
                                             const float* __restrict__ ws,
                                             __half2* __restrict__ out,
                                             int start, int stride) {
    constexpr int total4 = (N * K) >> 2;
    for (int i = start; i < total4; i += stride) {
        int e = i << 2;
        int n = e / K;          // compile-time K -> strength-reduced
        int k = e - n * K;
        float s = ws[(n >> 7) * (K >> 7) + (k >> 7)];
        float4 v = wq[i];
        out[2 * i]     = __floats2half2_rn(v.x * s, v.y * s);
        out[2 * i + 1] = __floats2half2_rn(v.z * s, v.w * s);
    }
}

// ---------------- prep kernel: x cvt + w1/w3 dequant ---------------------------
__global__ void prep_kernel(const float4* __restrict__ x,    __half2* __restrict__ xh,
                            const float4* __restrict__ w1q,  const float* __restrict__ w1s,
                            __half2* __restrict__ w1h,
                            const float4* __restrict__ w3q,  const float* __restrict__ w3s,
                            __half2* __restrict__ w3h) {
    const int start = blockIdx.x * blockDim.x + threadIdx.x;
    const int stride = gridDim.x * blockDim.x;
    switch (blockIdx.y) {
        case 0: {
            constexpr int n4 = (T_DIM * H_DIM) >> 2;
            for (int i = start; i < n4; i += stride) {
                float4 v = x[i];
                xh[2 * i]     = __floats2half2_rn(v.x, v.y);
                xh[2 * i + 1] = __floats2half2_rn(v.z, v.w);
            }
            break;
        }
        case 1: dequant_span<F_DIM, H_DIM>(w1q, w1s, w1h, start, stride); break;
        default: dequant_span<F_DIM, H_DIM>(w3q, w3s, w3h, start, stride); break;
    }
}

// ---------------- shared tile loader ------------------------------------------
// Load a 128x128-half tile as two 64-col SW128 subtiles (16KB each) at sbase.
__device__ __forceinline__ void load_tile128x128(const __half* g, int ld, int ko,
                                                 uint32_t sbase, int tid) {
    #pragma unroll
    for (int i = tid; i < 2048; i += 512) {
        int r = i >> 4;
        int q = i & 15;
        int sub = q >> 3, cc = q & 7;
        cp16(sbase + (uint32_t)sub * 16384 + SW128(r * 128 + cc * 16),
             g + (size_t)r * ld + ko + sub * 64 + cc * 8);
    }
}

// ---------------- GEMM1: dual-B HMMA + piggybacked w2 dequant ------------------
// blockIdx.y <  F_DIM/128 : GEMM C[128,128] tile (w1,w3 dual, silu*mul epilogue)
// blockIdx.y >= F_DIM/128 : dequant-only CTA for w2 (launches last -> tail wave)
#define GEMM1_BN (F_DIM / 128)   // 56
#define DQ_ROWS 4                // 4 x 32 = 128 dequant CTAs

__global__ void __launch_bounds__(512, 1)
gemm_dualB(const __half* __restrict__ A, const __half* __restrict__ B0g,
           const __half* __restrict__ B1g, __half* __restrict__ outH,
           int K, int Nglobal,
           const float4* __restrict__ w2q, const float* __restrict__ w2s,
           __half2* __restrict__ w2h) {
    const int tid = threadIdx.x;
    const int bm = blockIdx.x, bn = blockIdx.y;

    if (bn >= GEMM1_BN) {   // w2 dequant CTA — no smem, pure HBM, fills tail wave
        const int dqbid = (bn - GEMM1_BN) * gridDim.x + bm;       // 0..127
        dequant_span<H_DIM, F_DIM>(w2q, w2s, w2h,
                                   dqbid * 512 + tid, (gridDim.x * DQ_ROWS) * 512);
        return;
    }

    extern __shared__ __align__(1024) char smem[];
    const uint32_t sb = smem_u32(smem);
    const int lane = tid & 31, warp = tid >> 5;
    const int wm = warp >> 2, wn = warp & 3;
    const int NK = K >> 7;               // BK = 128
    const uint32_t STAGE = 98304;        // A(32K) + B0(32K) + B1(32K)

    const __half* Ag  = A   + (size_t)(bm * 128) * K;
    const __half* Bg0 = B0g + (size_t)(bn * 128) * K;
    const __half* Bg1 = B1g + (size_t)(bn * 128) * K;

    const int qr = lane >> 3, rin = lane & 7;
    const uint32_t swx    = (uint32_t)rin << 4;
    const uint32_t laneAr = (uint32_t)((qr & 1) * 1024 + rin * 128);
    const uint32_t kqA    = (uint32_t)((qr >> 1) << 4);
    const uint32_t laneBr = (uint32_t)((lane >> 4) * 1024 + rin * 128);
    const uint32_t kqB    = (uint32_t)(((lane >> 3) & 1) << 4);

    float acc0[2][4][4], acc1[2][4][4];
    #pragma unroll
    for (int mf = 0; mf < 2; mf++)
        #pragma unroll
        for (int nf = 0; nf < 4; nf++)
            #pragma unroll
            for (int i = 0; i < 4; i++) { acc0[mf][nf][i] = 0.f; acc1[mf][nf][i] = 0.f; }

    auto load_chunk = [&](int c, int buf) {
        const uint32_t st = sb + (uint32_t)buf * STAGE;
        const int ko = c << 7;
        load_tile128x128(Ag,  K, ko, st,          tid);
        load_tile128x128(Bg0, K, ko, st + 32768,  tid);
        load_tile128x128(Bg1, K, ko, st + 65536,  tid);
        asm volatile("cp.async.commit_group;\n");
    };

    load_chunk(0, 0);

    for (int kt = 0; kt < NK; kt++) {
        if (kt + 1 < NK) {
            load_chunk(kt + 1, (kt + 1) & 1);          // issue first...
            asm volatile("cp.async.wait_group 1;\n");  // ...then wait for chunk kt
        } else {
            asm volatile("cp.async.wait_group 0;\n");
        }
        __syncthreads();

        const uint32_t st = sb + (uint32_t)(kt & 1) * STAGE;

        #pragma unroll
        for (int ks = 0; ks < 8; ks++) {
            const uint32_t subo = (uint32_t)(ks >> 2) * 16384;
            const int kk = ks & 3;
            const uint32_t Abase  = st + subo + wm * 4096 + laneAr;
            const uint32_t B0base = st + 32768 + subo + wn * 4096 + laneBr;
            const uint32_t B1base = st + 65536 + subo + wn * 4096 + laneBr;
            const uint32_t acol = ((uint32_t)(kk * 32) + kqA) ^ swx;
            const uint32_t bcol = ((uint32_t)(kk * 32) + kqB) ^ swx;

            uint32_t a[2][4], b0[2][4], b1[2][4];
            ldsm4(a[0], Abase + acol);
            ldsm4(a[1], Abase + 2048 + acol);
            ldsm4(b0[0], B0base + bcol);
            ldsm4(b0[1], B0base + 2048 + bcol);
            ldsm4(b1[0], B1base + bcol);
            ldsm4(b1[1], B1base + 2048 + bcol);

            #pragma unroll
            for (int mf = 0; mf < 2; mf++)
                #pragma unroll
                for (int nf = 0; nf < 4; nf++) {
                    const uint32_t bb[2] = { b0[nf >> 1][(nf & 1) * 2],
                                             b0[nf >> 1][(nf & 1) * 2 + 1] };
                    mma16816(acc0[mf][nf], a[mf], bb);
                }
            #pragma unroll
            for (int mf = 0; mf < 2; mf++)
                #pragma unroll
                for (int nf = 0; nf < 4; nf++) {
                    const uint32_t bc[2] = { b1[nf >> 1][(nf & 1) * 2],
                                             b1[nf >> 1][(nf & 1) * 2 + 1] };
                    mma16816(acc1[mf][nf], a[mf], bc);
                }
        }
        __syncthreads();
    }

    const int g = lane >> 2, t = lane & 3;
    const int row0 = bm * 128 + wm * 32;
    const int col0 = bn * 128 + wn * 32;
    #pragma unroll
    for (int mf = 0; mf < 2; mf++) {
        #pragma unroll
        for (int nf = 0; nf < 4; nf++) {
            const int r = row0 + mf * 16 + g;
            const int c = col0 + nf * 8 + 2 * t;
            float s0 = silu_f(acc0[mf][nf][0]) * acc1[mf][nf][0];
            float s1 = silu_f(acc0[mf][nf][1]) * acc1[mf][nf][1];
            float s2 = silu_f(acc0[mf][nf][2]) * acc1[mf][nf][2];
            float s3 = silu_f(acc0[mf][nf][3]) * acc1[mf][nf][3];
            *(__half2*)(outH + (size_t)r * Nglobal + c)       = __floats2half2_rn(s0, s1);
            *(__half2*)(outH + (size_t)(r + 8) * Nglobal + c) = __floats2half2_rn(s2, s3);
        }
    }
}

// ---------------- GEMM2: dual-A HMMA (16 warps, warp tile 32x32, 2 M-halves) ---
__global__ void __launch_bounds__(512, 1)
gemm_dualA(const __half* __restrict__ A, const __half* __restrict__ Bg,
           float* __restrict__ outF, int K, int Nglobal) {
    extern __shared__ __align__(1024) char smem[];
    const uint32_t sb = smem_u32(smem);
    const int tid = threadIdx.x, lane = tid & 31, warp = tid >> 5;
    const int wm = warp >> 2, wn = warp & 3;
    const int bm = blockIdx.x, bn = blockIdx.y;
    const int NK = K >> 7;
    const uint32_t STAGE = 98304;        // A0(32K) + A1(32K) + B(32K)

    const __half* Ag0 = A  + (size_t)(bm * 256) * K;
    const __half* Ag1 = Ag0 + (size_t)128 * K;
    const __half* Bg0 = Bg + (size_t)(bn * 128) * K;

    const int qr = lane >> 3, rin = lane & 7;
    const uint32_t swx    = (uint32_t)rin << 4;
    const uint32_t laneAr = (uint32_t)((qr & 1) * 1024 + rin * 128);
    const uint32_t kqA    = (uint32_t)((qr >> 1) << 4);
    const uint32_t laneBr = (uint32_t)((lane >> 4) * 1024 + rin * 128);
    const uint32_t kqB    = (uint32_t)(((lane >> 3) & 1) << 4);

    float acc0[2][4][4], acc1[2][4][4];
    #pragma unroll
    for (int mf = 0; mf < 2; mf++)
        #pragma unroll
        for (int nf = 0; nf < 4; nf++)
            #pragma unroll
            for (int i = 0; i < 4; i++) { acc0[mf][nf][i] = 0.f; acc1[mf][nf][i] = 0.f; }

    auto load_chunk = [&](int c, int buf) {
        const uint32_t st = sb + (uint32_t)buf * STAGE;
        const int ko = c << 7;
        load_tile128x128(Ag0, K, ko, st,          tid);
        load_tile128x128(Ag1, K, ko, st + 32768,  tid);
        load_tile128x128(Bg0, K, ko, st + 65536,  tid);
        asm volatile("cp.async.commit_group;\n");
    };

    load_chunk(0, 0);

    for (int kt = 0; kt < NK; kt++) {
        if (kt + 1 < NK) {
            load_chunk(kt + 1, (kt + 1) & 1);
            asm volatile("cp.async.wait_group 1;\n");
        } else {
            asm volatile("cp.async.wait_group 0;\n");
        }
        __syncthreads();

        const uint32_t st = sb + (uint32_t)(kt & 1) * STAGE;

        #pragma unroll
        for (int ks = 0; ks < 8; ks++) {
            const uint32_t subo = (uint32_t)(ks >> 2) * 16384;
            const int kk = ks & 3;
            const uint32_t A0base = st + subo + wm * 4096 + laneAr;
            const uint32_t A1base = st + 32768 + subo + wm * 4096 + laneAr;
            const uint32_t Bbase  = st + 65536 + subo + wn * 4096 + laneBr;
            const uint32_t acol = ((uint32_t)(kk * 32) + kqA) ^ swx;
            const uint32_t bcol = ((uint32_t)(kk * 32) + kqB) ^ swx;

            uint32_t a0[2][4], a1[2][4], b[2][4];
            ldsm4(a0[0], A0base + acol);
            ldsm4(a0[1], A0base + 2048 + acol);
            ldsm4(a1[0], A1base + acol);
            ldsm4(a1[1], A1base + 2048 + acol);
            ldsm4(b[0], Bbase + bcol);
            ldsm4(b[1], Bbase + 2048 + bcol);

            #pragma unroll
            for (int mf = 0; mf < 2; mf++)
                #pragma unroll
                for (int nf = 0; nf < 4; nf++) {
                    const uint32_t bb[2] = { b[nf >> 1][(nf & 1) * 2],
                                             b[nf >> 1][(nf & 1) * 2 + 1] };
                    mma16816(acc0[mf][nf], a0[mf], bb);
                }
            #pragma unroll
            for (int mf = 0; mf < 2; mf++)
                #pragma unroll
                for (int nf = 0; nf < 4; nf++) {
                    const uint32_t bb[2] = { b[nf >> 1][(nf & 1) * 2],
                                             b[nf >> 1][(nf & 1) * 2 + 1] };
                    mma16816(acc1[mf][nf], a1[mf], bb);
                }
        }
        __syncthreads();
    }

    const int g = lane >> 2, t = lane & 3;
    const int row0 = bm * 256 + wm * 32;
    const int col0 = bn * 128 + wn * 32;
    #pragma unroll
    for (int mf = 0; mf < 2; mf++) {
        #pragma unroll
        for (int nf = 0; nf < 4; nf++) {
            const int r = row0 + mf * 16 + g;
            const int c = col0 + nf * 8 + 2 * t;
            *(float2*)(outF + (size_t)r * Nglobal + c) =
                make_float2(acc0[mf][nf][0], acc0[mf][nf][1]);
            *(float2*)(outF + (size_t)(r + 8) * Nglobal + c) =
                make_float2(acc0[mf][nf][2], acc0[mf][nf][3]);
            *(float2*)(outF + (size_t)(r + 128) * Nglobal + c) =
                make_float2(acc1[mf][nf][0], acc1[mf][nf][1]);
            *(float2*)(outF + (size_t)(r + 136) * Nglobal + c) =
                make_float2(acc1[mf][nf][2], acc1[mf][nf][3]);
        }
    }
}

// ---------------- launch ------------------------------------------------------
extern "C" void kernel_launch(void* const* d_in, const int* in_sizes, int n_in,
                              void* d_out, int out_size) {
    const float* x   = (const float*)d_in[0];  // [T,H]
    const float* w1q = (const float*)d_in[1];  // [F,H]
    const float* w1s = (const float*)d_in[2];
    const float* w3q = (const float*)d_in[3];  // [F,H]
    const float* w3s = (const float*)d_in[4];
    const float* w2q = (const float*)d_in[5];  // [H,F]
    const float* w2s = (const float*)d_in[6];

    __half *xh, *w1h, *w3h, *w2h, *fused;
    cudaGetSymbolAddress((void**)&xh,    g_xh);
    cudaGetSymbolAddress((void**)&w1h,   g_w1h);
    cudaGetSymbolAddress((void**)&w3h,   g_w3h);
    cudaGetSymbolAddress((void**)&w2h,   g_w2h);
    cudaGetSymbolAddress((void**)&fused, g_fused);

    const int SMEM = 2 * 98304;  // 196608 B
    cudaFuncSetAttribute((const void*)gemm_dualB,
                         cudaFuncAttributeMaxDynamicSharedMemorySize, SMEM);
    cudaFuncSetAttribute((const void*)gemm_dualA,
                         cudaFuncAttributeMaxDynamicSharedMemorySize, SMEM);

    // 1) prep: x->fp16 + dequant w1/w3 (w2 folded into GEMM1's tail wave)
    {
        dim3 grid(1024, 3);
        prep_kernel<<<grid, 256>>>((const float4*)x, (__half2*)xh,
                                   (const float4*)w1q, w1s, (__half2*)w1h,
                                   (const float4*)w3q, w3s, (__half2*)w3h);
    }
    // 2) fused dual-B GEMM (+ w2 dequant CTAs): fused = silu(x@w1^T)*(x@w3^T)
    {
        dim3 grid(T_DIM / 128, GEMM1_BN + DQ_ROWS);
        gemm_dualB<<<grid, 512, SMEM>>>(xh, w1h, w3h, fused, H_DIM, F_DIM,
                                        (const float4*)w2q, w2s, (__half2*)w2h);
    }
    // 3) out = fused @ w2^T   [T,H] f32  (dual-A: 256-row CTA tiles share B)
    {
        dim3 grid(T_DIM / 256, H_DIM / 128);
        gemm_dualA<<<grid, 512, SMEM>>>(fused, w2h, (float*)d_out, F_DIM, H_DIM);
    }
}

// round 13
// speedup vs baseline: 1.0231x; 1.0231x over previous
#include <cuda_runtime.h>
#include <cuda_fp16.h>
#include <cstdint>

#define T_DIM 4096
#define H_DIM 2048
#define F_DIM 7168

// ---------------- scratch (device globals; no runtime allocation) ------------
__device__ __align__(1024) __half g_xh  [(size_t)T_DIM * H_DIM];   // x  fp16 [T,H]
__device__ __align__(1024) __half g_w1h [(size_t)F_DIM * H_DIM];   // w1 fp16 [F,H]
__device__ __align__(1024) __half g_w3h [(size_t)F_DIM * H_DIM];   // w3 fp16 [F,H]
__device__ __align__(1024) __half g_w2h [(size_t)H_DIM * F_DIM];   // w2 fp16 [H,F]
__device__ __align__(1024) __half g_fused[(size_t)T_DIM * F_DIM];  // silu(g)*u fp16 [T,F]

// ---------------- helpers -----------------------------------------------------
__device__ __forceinline__ float silu_f(float v) { return v / (1.0f + __expf(-v)); }

__device__ __forceinline__ uint32_t smem_u32(const void* p) {
    uint32_t a;
    asm("{ .reg .u64 t; cvta.to.shared.u64 t, %1; cvt.u32.u64 %0, t; }" : "=r"(a) : "l"(p));
    return a;
}

#define SW128(o) ((o) ^ (((o) >> 3) & 0x70))

__device__ __forceinline__ void cp16(uint32_t dst, const void* src) {
    asm volatile("cp.async.cg.shared.global [%0], [%1], 16;\n" :: "r"(dst), "l"(src));
}

__device__ __forceinline__ void mma16816(float c[4], const uint32_t a[4], const uint32_t b[2]) {
    asm volatile(
        "mma.sync.aligned.m16n8k16.row.col.f32.f16.f16.f32 "
        "{%0,%1,%2,%3}, {%4,%5,%6,%7}, {%8,%9}, {%0,%1,%2,%3};\n"
        : "+f"(c[0]), "+f"(c[1]), "+f"(c[2]), "+f"(c[3])
        : "r"(a[0]), "r"(a[1]), "r"(a[2]), "r"(a[3]), "r"(b[0]), "r"(b[1]));
}

__device__ __forceinline__ void ldsm4(uint32_t* r, uint32_t addr) {
    asm volatile("ldmatrix.sync.aligned.m8n8.x4.shared.b16 {%0,%1,%2,%3}, [%4];"
                 : "=r"(r[0]), "=r"(r[1]), "=r"(r[2]), "=r"(r[3]) : "r"(addr));
}

// ---------------- merged prep kernel ------------------------------------------
// blockIdx.y selects region: 0 = cvt x, 1 = dequant w1, 2 = w3, 3 = w2.
// Reads use __ldcs (streaming, never reused). w2h writes use __stcs so they
// don't evict xh/w1h/w3h (which fit in L2 and feed GEMM1's first wave).
template <int N, int K, bool STREAM_OUT>
__device__ __forceinline__ void dequant_body(const float4* __restrict__ wq,
                                             const float* __restrict__ ws,
                                             __half2* __restrict__ out) {
    constexpr int total4 = (N * K) >> 2;
    for (int i = blockIdx.x * blockDim.x + threadIdx.x; i < total4;
         i += gridDim.x * blockDim.x) {
        int e = i << 2;
        int n = e / K;          // compile-time K -> strength-reduced
        int k = e - n * K;
        float s = ws[(n >> 7) * (K >> 7) + (k >> 7)];
        float4 v = __ldcs(&wq[i]);
        __half2 h0 = __floats2half2_rn(v.x * s, v.y * s);
        __half2 h1 = __floats2half2_rn(v.z * s, v.w * s);
        if (STREAM_OUT) {
            __stcs(&out[2 * i], h0);
            __stcs(&out[2 * i + 1], h1);
        } else {
            out[2 * i]     = h0;
            out[2 * i + 1] = h1;
        }
    }
}

__global__ void prep_kernel(const float4* __restrict__ x,    __half2* __restrict__ xh,
                            const float4* __restrict__ w1q,  const float* __restrict__ w1s,
                            __half2* __restrict__ w1h,
                            const float4* __restrict__ w3q,  const float* __restrict__ w3s,
                            __half2* __restrict__ w3h,
                            const float4* __restrict__ w2q,  const float* __restrict__ w2s,
                            __half2* __restrict__ w2h) {
    switch (blockIdx.y) {
        case 0: {
            constexpr int n4 = (T_DIM * H_DIM) >> 2;
            for (int i = blockIdx.x * blockDim.x + threadIdx.x; i < n4;
                 i += gridDim.x * blockDim.x) {
                float4 v = __ldcs(&x[i]);
                xh[2 * i]     = __floats2half2_rn(v.x, v.y);
                xh[2 * i + 1] = __floats2half2_rn(v.z, v.w);
            }
            break;
        }
        case 1: dequant_body<F_DIM, H_DIM, false>(w1q, w1s, w1h); break;
        case 2: dequant_body<F_DIM, H_DIM, false>(w3q, w3s, w3h); break;
        default: dequant_body<H_DIM, F_DIM, true>(w2q, w2s, w2h); break;
    }
}

// ---------------- shared tile loader ------------------------------------------
// Load a 128x128-half tile as two 64-col SW128 subtiles (16KB each) at sbase.
__device__ __forceinline__ void load_tile128x128(const __half* g, int ld, int ko,
                                                 uint32_t sbase, int tid) {
    #pragma unroll
    for (int i = tid; i < 2048; i += 512) {
        int r = i >> 4;
        int q = i & 15;
        int sub = q >> 3, cc = q & 7;
        cp16(sbase + (uint32_t)sub * 16384 + SW128(r * 128 + cc * 16),
             g + (size_t)r * ld + ko + sub * 64 + cc * 8);
    }
}

// ---------------- GEMM1: dual-B HMMA (16 warps, warp tile 32x32) ---------------
__global__ void __launch_bounds__(512, 1)
gemm_dualB(const __half* __restrict__ A, const __half* __restrict__ B0g,
           const __half* __restrict__ B1g, __half* __restrict__ outH,
           int K, int Nglobal) {
    extern __shared__ __align__(1024) char smem[];
    const uint32_t sb = smem_u32(smem);
    const int tid = threadIdx.x, lane = tid & 31, warp = tid >> 5;
    const int wm = warp >> 2, wn = warp & 3;
    const int bm = blockIdx.x, bn = blockIdx.y;
    const int NK = K >> 7;               // BK = 128
    const uint32_t STAGE = 98304;        // A(32K) + B0(32K) + B1(32K)

    const __half* Ag  = A   + (size_t)(bm * 128) * K;
    const __half* Bg0 = B0g + (size_t)(bn * 128) * K;
    const __half* Bg1 = B1g + (size_t)(bn * 128) * K;

    const int qr = lane >> 3, rin = lane & 7;
    const uint32_t swx    = (uint32_t)rin << 4;
    const uint32_t laneAr = (uint32_t)((qr & 1) * 1024 + rin * 128);
    const uint32_t kqA    = (uint32_t)((qr >> 1) << 4);
    const uint32_t laneBr = (uint32_t)((lane >> 4) * 1024 + rin * 128);
    const uint32_t kqB    = (uint32_t)(((lane >> 3) & 1) << 4);

    float acc0[2][4][4], acc1[2][4][4];
    #pragma unroll
    for (int mf = 0; mf < 2; mf++)
        #pragma unroll
        for (int nf = 0; nf < 4; nf++)
            #pragma unroll
            for (int i = 0; i < 4; i++) { acc0[mf][nf][i] = 0.f; acc1[mf][nf][i] = 0.f; }

    auto load_chunk = [&](int c, int buf) {
        const uint32_t st = sb + (uint32_t)buf * STAGE;
        const int ko = c << 7;
        load_tile128x128(Ag,  K, ko, st,          tid);
        load_tile128x128(Bg0, K, ko, st + 32768,  tid);
        load_tile128x128(Bg1, K, ko, st + 65536,  tid);
        asm volatile("cp.async.commit_group;\n");
    };

    load_chunk(0, 0);

    for (int kt = 0; kt < NK; kt++) {
        if (kt + 1 < NK) {
            load_chunk(kt + 1, (kt + 1) & 1);          // issue first...
            asm volatile("cp.async.wait_group 1;\n");  // ...then wait for chunk kt
        } else {
            asm volatile("cp.async.wait_group 0;\n");
        }
        __syncthreads();

        const uint32_t st = sb + (uint32_t)(kt & 1) * STAGE;

        #pragma unroll
        for (int ks = 0; ks < 8; ks++) {
            const uint32_t subo = (uint32_t)(ks >> 2) * 16384;
            const int kk = ks & 3;
            const uint32_t Abase  = st + subo + wm * 4096 + laneAr;
            const uint32_t B0base = st + 32768 + subo + wn * 4096 + laneBr;
            const uint32_t B1base = st + 65536 + subo + wn * 4096 + laneBr;
            const uint32_t acol = ((uint32_t)(kk * 32) + kqA) ^ swx;
            const uint32_t bcol = ((uint32_t)(kk * 32) + kqB) ^ swx;

            uint32_t a[2][4], b0[2][4], b1[2][4];
            ldsm4(a[0], Abase + acol);
            ldsm4(a[1], Abase + 2048 + acol);
            ldsm4(b0[0], B0base + bcol);
            ldsm4(b0[1], B0base + 2048 + bcol);
            ldsm4(b1[0], B1base + bcol);
            ldsm4(b1[1], B1base + 2048 + bcol);

            #pragma unroll
            for (int mf = 0; mf < 2; mf++)
                #pragma unroll
                for (int nf = 0; nf < 4; nf++) {
                    const uint32_t bb[2] = { b0[nf >> 1][(nf & 1) * 2],
                                             b0[nf >> 1][(nf & 1) * 2 + 1] };
                    mma16816(acc0[mf][nf], a[mf], bb);
                }
            #pragma unroll
            for (int mf = 0; mf < 2; mf++)
                #pragma unroll
                for (int nf = 0; nf < 4; nf++) {
                    const uint32_t bc[2] = { b1[nf >> 1][(nf & 1) * 2],
                                             b1[nf >> 1][(nf & 1) * 2 + 1] };
                    mma16816(acc1[mf][nf], a[mf], bc);
                }
        }
        __syncthreads();
    }

    const int g = lane >> 2, t = lane & 3;
    const int row0 = bm * 128 + wm * 32;
    const int col0 = bn * 128 + wn * 32;
    #pragma unroll
    for (int mf = 0; mf < 2; mf++) {
        #pragma unroll
        for (int nf = 0; nf < 4; nf++) {
            const int r = row0 + mf * 16 + g;
            const int c = col0 + nf * 8 + 2 * t;
            float s0 = silu_f(acc0[mf][nf][0]) * acc1[mf][nf][0];
            float s1 = silu_f(acc0[mf][nf][1]) * acc1[mf][nf][1];
            float s2 = silu_f(acc0[mf][nf][2]) * acc1[mf][nf][2];
            float s3 = silu_f(acc0[mf][nf][3]) * acc1[mf][nf][3];
            *(__half2*)(outH + (size_t)r * Nglobal + c)       = __floats2half2_rn(s0, s1);
            *(__half2*)(outH + (size_t)(r + 8) * Nglobal + c) = __floats2half2_rn(s2, s3);
        }
    }
}

// ---------------- GEMM2: dual-A HMMA (16 warps, warp tile 32x32, 2 M-halves) ---
__global__ void __launch_bounds__(512, 1)
gemm_dualA(const __half* __restrict__ A, const __half* __restrict__ Bg,
           float* __restrict__ outF, int K, int Nglobal) {
    extern __shared__ __align__(1024) char smem[];
    const uint32_t sb = smem_u32(smem);
    const int tid = threadIdx.x, lane = tid & 31, warp = tid >> 5;
    const int wm = warp >> 2, wn = warp & 3;
    const int bm = blockIdx.x, bn = blockIdx.y;
    const int NK = K >> 7;
    const uint32_t STAGE = 98304;        // A0(32K) + A1(32K) + B(32K)

    const __half* Ag0 = A  + (size_t)(bm * 256) * K;
    const __half* Ag1 = Ag0 + (size_t)128 * K;
    const __half* Bg0 = Bg + (size_t)(bn * 128) * K;

    const int qr = lane >> 3, rin = lane & 7;
    const uint32_t swx    = (uint32_t)rin << 4;
    const uint32_t laneAr = (uint32_t)((qr & 1) * 1024 + rin * 128);
    const uint32_t kqA    = (uint32_t)((qr >> 1) << 4);
    const uint32_t laneBr = (uint32_t)((lane >> 4) * 1024 + rin * 128);
    const uint32_t kqB    = (uint32_t)(((lane >> 3) & 1) << 4);

    float acc0[2][4][4], acc1[2][4][4];
    #pragma unroll
    for (int mf = 0; mf < 2; mf++)
        #pragma unroll
        for (int nf = 0; nf < 4; nf++)
            #pragma unroll
            for (int i = 0; i < 4; i++) { acc0[mf][nf][i] = 0.f; acc1[mf][nf][i] = 0.f; }

    auto load_chunk = [&](int c, int buf) {
        const uint32_t st = sb + (uint32_t)buf * STAGE;
        const int ko = c << 7;
        load_tile128x128(Ag0, K, ko, st,          tid);
        load_tile128x128(Ag1, K, ko, st + 32768,  tid);
        load_tile128x128(Bg0, K, ko, st + 65536,  tid);
        asm volatile("cp.async.commit_group;\n");
    };

    load_chunk(0, 0);

    for (int kt = 0; kt < NK; kt++) {
        if (kt + 1 < NK) {
            load_chunk(kt + 1, (kt + 1) & 1);
            asm volatile("cp.async.wait_group 1;\n");
        } else {
            asm volatile("cp.async.wait_group 0;\n");
        }
        __syncthreads();

        const uint32_t st = sb + (uint32_t)(kt & 1) * STAGE;

        #pragma unroll
        for (int ks = 0; ks < 8; ks++) {
            const uint32_t subo = (uint32_t)(ks >> 2) * 16384;
            const int kk = ks & 3;
            const uint32_t A0base = st + subo + wm * 4096 + laneAr;
            const uint32_t A1base = st + 32768 + subo + wm * 4096 + laneAr;
            const uint32_t Bbase  = st + 65536 + subo + wn * 4096 + laneBr;
            const uint32_t acol = ((uint32_t)(kk * 32) + kqA) ^ swx;
            const uint32_t bcol = ((uint32_t)(kk * 32) + kqB) ^ swx;

            uint32_t a0[2][4], a1[2][4], b[2][4];
            ldsm4(a0[0], A0base + acol);
            ldsm4(a0[1], A0base + 2048 + acol);
            ldsm4(a1[0], A1base + acol);
            ldsm4(a1[1], A1base + 2048 + acol);
            ldsm4(b[0], Bbase + bcol);
            ldsm4(b[1], Bbase + 2048 + bcol);

            #pragma unroll
            for (int mf = 0; mf < 2; mf++)
                #pragma unroll
                for (int nf = 0; nf < 4; nf++) {
                    const uint32_t bb[2] = { b[nf >> 1][(nf & 1) * 2],
                                             b[nf >> 1][(nf & 1) * 2 + 1] };
                    mma16816(acc0[mf][nf], a0[mf], bb);
                }
            #pragma unroll
            for (int mf = 0; mf < 2; mf++)
                #pragma unroll
                for (int nf = 0; nf < 4; nf++) {
                    const uint32_t bb[2] = { b[nf >> 1][(nf & 1) * 2],
                                             b[nf >> 1][(nf & 1) * 2 + 1] };
                    mma16816(acc1[mf][nf], a1[mf], bb);
                }
        }
        __syncthreads();
    }

    const int g = lane >> 2, t = lane & 3;
    const int row0 = bm * 256 + wm * 32;
    const int col0 = bn * 128 + wn * 32;
    #pragma unroll
    for (int mf = 0; mf < 2; mf++) {
        #pragma unroll
        for (int nf = 0; nf < 4; nf++) {
            const int r = row0 + mf * 16 + g;
            const int c = col0 + nf * 8 + 2 * t;
            *(float2*)(outF + (size_t)r * Nglobal + c) =
                make_float2(acc0[mf][nf][0], acc0[mf][nf][1]);
            *(float2*)(outF + (size_t)(r + 8) * Nglobal + c) =
                make_float2(acc0[mf][nf][2], acc0[mf][nf][3]);
            *(float2*)(outF + (size_t)(r + 128) * Nglobal + c) =
                make_float2(acc1[mf][nf][0], acc1[mf][nf][1]);
            *(float2*)(outF + (size_t)(r + 136) * Nglobal + c) =
                make_float2(acc1[mf][nf][2], acc1[mf][nf][3]);
        }
    }
}

// ---------------- launch ------------------------------------------------------
extern "C" void kernel_launch(void* const* d_in, const int* in_sizes, int n_in,
                              void* d_out, int out_size) {
    const float* x   = (const float*)d_in[0];  // [T,H]
    const float* w1q = (const float*)d_in[1];  // [F,H]
    const float* w1s = (const float*)d_in[2];
    const float* w3q = (const float*)d_in[3];  // [F,H]
    const float* w3s = (const float*)d_in[4];
    const float* w2q = (const float*)d_in[5];  // [H,F]
    const float* w2s = (const float*)d_in[6];

    __half *xh, *w1h, *w3h, *w2h, *fused;
    cudaGetSymbolAddress((void**)&xh,    g_xh);
    cudaGetSymbolAddress((void**)&w1h,   g_w1h);
    cudaGetSymbolAddress((void**)&w3h,   g_w3h);
    cudaGetSymbolAddress((void**)&w2h,   g_w2h);
    cudaGetSymbolAddress((void**)&fused, g_fused);

    const int SMEM = 2 * 98304;  // 196608 B
    cudaFuncSetAttribute((const void*)gemm_dualB,
                         cudaFuncAttributeMaxDynamicSharedMemorySize, SMEM);
    cudaFuncSetAttribute((const void*)gemm_dualA,
                         cudaFuncAttributeMaxDynamicSharedMemorySize, SMEM);

    // 1) merged prep: x->fp16 + dequant w1/w3/w2 -> fp16, single launch
    {
        dim3 grid(1024, 4);
        prep_kernel<<<grid, 256>>>((const float4*)x, (__half2*)xh,
                                   (const float4*)w1q, w1s, (__half2*)w1h,
                                   (const float4*)w3q, w3s, (__half2*)w3h,
                                   (const float4*)w2q, w2s, (__half2*)w2h);
    }
    // 2) fused dual-B GEMM: fused = silu(x@w1^T) * (x@w3^T)   [T,F] f16
    {
        dim3 grid(T_DIM / 128, F_DIM / 128);
        gemm_dualB<<<grid, 512, SMEM>>>(xh, w1h, w3h, fused, H_DIM, F_DIM);
    }
    // 3) out = fused @ w2^T   [T,H] f32  (dual-A: 256-row CTA tiles share B)
    {
        dim3 grid(T_DIM / 256, H_DIM / 128);
        gemm_dualA<<<grid, 512, SMEM>>>(fused, w2h, (float*)d_out, F_DIM, H_DIM);
    }
}